// round 7
// baseline (speedup 1.0000x reference)
#include <cuda_runtime.h>
#include <math.h>
#include <stdint.h>

#define HASH_SIZE  (1u << 19)
#define HASH_MASK  (HASH_SIZE - 1u)
#define NT 128
#define NBINS (1 << 18)
#define MAXPTS (1 << 20)

// smem u32 layout sizes
#define SW0_N  (72*72)
#define SW1_N  (64*72)
#define SW2_N  (64*40)
#define SX_STRIDE 77
#define SX_WARP (32*SX_STRIDE)
#define SX_N   (4*SX_WARP)

struct LParams {
    float rm1[16];
    int   R[16];
    int   dense[16];
};

// ---- static scratch ----
__device__ int g_bins[NBINS];
__device__ int g_cnt[NBINS];
__device__ int g_binStart[NBINS];
__device__ int g_partials[256];
__device__ int g_keys[MAXPTS];
__device__ int g_perm[MAXPTS];

__device__ __forceinline__ float sp100(float v) {
    float z = v * 100.0f;
    float s = 0.01f * __logf(1.0f + __expf(z));
    return (z > 20.0f) ? v : s;
}
__device__ __forceinline__ uint32_t tf32_of(float f) {
    uint32_t u; asm("cvt.rna.tf32.f32 %0, %1;" : "=r"(u) : "f"(f)); return u;
}
__device__ __forceinline__ void mma_tf32(float c[4], uint32_t a0, uint32_t a1,
                                         uint32_t a2, uint32_t a3,
                                         uint32_t b0, uint32_t b1) {
    asm("mma.sync.aligned.m16n8k8.row.col.f32.tf32.tf32.f32 "
        "{%0,%1,%2,%3}, {%4,%5,%6,%7}, {%8,%9}, {%0,%1,%2,%3};"
        : "+f"(c[0]), "+f"(c[1]), "+f"(c[2]), "+f"(c[3])
        : "r"(a0), "r"(a1), "r"(a2), "r"(a3), "r"(b0), "r"(b1));
}

// ---------------- sort pipeline ----------------
__device__ __forceinline__ uint32_t part3(uint32_t x) {
    x &= 0x3Fu;
    x = (x | (x << 16)) & 0x030000FFu;
    x = (x | (x << 8))  & 0x0300F00Fu;
    x = (x | (x << 4))  & 0x030C30C3u;
    x = (x | (x << 2))  & 0x09249249u;
    return x;
}
__global__ void k_zero() {
    int i = blockIdx.x * blockDim.x + threadIdx.x;
    if (i < NBINS) { g_bins[i] = 0; g_cnt[i] = 0; }
}
__global__ void k_hist(const float* __restrict__ x, int npts) {
    int i = blockIdx.x * blockDim.x + threadIdx.x;
    if (i >= npts) return;
    float px = x[3*i], py = x[3*i+1], pz = x[3*i+2];
    int kx = min(max((int)(px * 64.0f), 0), 63);
    int ky = min(max((int)(py * 64.0f), 0), 63);
    int kz = min(max((int)(pz * 64.0f), 0), 63);
    uint32_t key = part3(kx) | (part3(ky) << 1) | (part3(kz) << 2);
    g_keys[i] = (int)key;
    atomicAdd(&g_bins[key], 1);
}
__global__ void k_scan1() {
    __shared__ int s[1024];
    int t = threadIdx.x;
    int g = blockIdx.x * 1024 + t;
    int v = g_bins[g];
    s[t] = v; __syncthreads();
#pragma unroll
    for (int d = 1; d < 1024; d <<= 1) {
        int add = (t >= d) ? s[t-d] : 0;
        __syncthreads();
        s[t] += add;
        __syncthreads();
    }
    g_binStart[g] = s[t] - v;
    if (t == 1023) g_partials[blockIdx.x] = s[t];
}
__global__ void k_scan2() {
    __shared__ int s[256];
    int t = threadIdx.x;
    int v = g_partials[t];
    s[t] = v; __syncthreads();
#pragma unroll
    for (int d = 1; d < 256; d <<= 1) {
        int add = (t >= d) ? s[t-d] : 0;
        __syncthreads();
        s[t] += add;
        __syncthreads();
    }
    g_partials[t] = s[t] - v;
}
__global__ void k_scan3() {
    int g = blockIdx.x * 1024 + threadIdx.x;
    g_binStart[g] += g_partials[blockIdx.x];
}
__global__ void k_scatter(int npts) {
    int i = blockIdx.x * blockDim.x + threadIdx.x;
    if (i >= npts) return;
    int k = g_keys[i];
    int pos = g_binStart[k] + atomicAdd(&g_cnt[k], 1);
    g_perm[pos] = i;
}

// ---------------- fused main kernel: scalar features + tf32 MMA MLP ----------------
__global__ void __launch_bounds__(NT, 2) nerf_fused(
    const float* __restrict__ xin,
    const float* __restrict__ tables,
    const float* __restrict__ W0, const float* __restrict__ b0,
    const float* __restrict__ W1, const float* __restrict__ b1,
    const float* __restrict__ W2, const float* __restrict__ b2,
    float* __restrict__ out, int npts, LParams lp)
{
    extern __shared__ uint32_t smu[];
    uint32_t* sW0 = smu;                 // [k:72][n:72 stride], tf32, B of layer0
    uint32_t* sW1 = sW0 + SW0_N;         // [k:64][n:72 stride]
    uint32_t* sW2 = sW1 + SW1_N;         // [k:64][n:40 stride]
    uint32_t* sX  = sW2 + SW2_N;         // 4 warps x [32][77]
    float* sb0f = (float*)(sX + SX_N);   // 64
    float* sb1f = sb0f + 64;             // 64
    float* sb2f = sb1f + 64;             // 24

    const int tid = threadIdx.x;

    // weight staging: B[k][n] = W^T, tf32
    for (int t = tid; t < 72*64; t += NT) {
        int k = t >> 6, n = t & 63;
        sW0[k*72 + n] = (k < 71) ? tf32_of(W0[n*71 + k]) : 0u;
    }
    for (int t = tid; t < 64*64; t += NT) {
        int k = t >> 6, n = t & 63;
        sW1[k*72 + n] = tf32_of(W1[n*64 + k]);
    }
    for (int t = tid; t < 64*24; t += NT) {
        int k = t / 24, n = t % 24;
        sW2[k*40 + n] = (n < 17) ? tf32_of(W2[n*64 + k]) : 0u;
    }
    if (tid < 64) { sb0f[tid] = b0[tid]; sb1f[tid] = b1[tid]; }
    if (tid < 24) sb2f[tid] = (tid < 17) ? b2[tid] : 0.0f;
    __syncthreads();

    const int warp = tid >> 5;
    const int lane = tid & 31;
    const int qg = lane >> 2;     // fragment group id (0..7)
    const int qc = lane & 3;      // thread-in-group (0..3)
    uint32_t* sXw = sX + warp * SX_WARP;

    const int warpbase = blockIdx.x * NT + warp * 32;
    const int gid = warpbase + lane;
    const int n = (gid < npts) ? g_perm[gid] : g_perm[0];

    const float px = xin[n*3+0], py = xin[n*3+1], pz = xin[n*3+2];
    uint32_t* myrow = sXw + lane * SX_STRIDE;

    // ---- feature generation (cols 0..71), stored as tf32 ----
    myrow[0] = tf32_of(px);
    myrow[1] = tf32_of(py);
    myrow[2] = tf32_of(pz);
    myrow[71] = 0u;

#pragma unroll 1
    for (int m = 0; m < 6; m++) {
        float f = (float)(1 << m);
        float ax = px * f, ay = py * f, az = pz * f;
        uint32_t* c = myrow + 3 + 6*m;
        c[0] = tf32_of(__sinf(ax));
        c[1] = tf32_of(__sinf(ay));
        c[2] = tf32_of(__sinf(az));
        c[3] = tf32_of(__cosf(ax));
        c[4] = tf32_of(__cosf(ay));
        c[5] = tf32_of(__cosf(az));
    }

#pragma unroll 1
    for (int l = 0; l < 16; l++) {
        const float rm1 = lp.rm1[l];
        const int   R   = lp.R[l];
        float fx = px * rm1, fy = py * rm1, fz = pz * rm1;
        float p0x = floorf(fx), p0y = floorf(fy), p0z = floorf(fz);
        float wx = fx - p0x, wy = fy - p0y, wz = fz - p0z;
        int ix = (int)p0x, iy = (int)p0y, iz = (int)p0z;
        int x0 = max(min(ix,     R-1), 0), x1 = max(min(ix + 1, R-1), 0);
        int y0 = max(min(iy,     R-1), 0), y1 = max(min(iy + 1, R-1), 0);
        int z0 = max(min(iz,     R-1), 0), z1 = max(min(iz + 1, R-1), 0);

        uint32_t i000, i001, i010, i011, i100, i101, i110, i111;
        if (lp.dense[l]) {
            int R2 = R * R;
            int az0 = z0 * R2, az1 = z1 * R2;
            int ay0 = y0 * R,  ay1 = y1 * R;
            i000 = (uint32_t)(x0 + ay0 + az0);
            i001 = (uint32_t)(x0 + ay0 + az1);
            i010 = (uint32_t)(x0 + ay1 + az0);
            i011 = (uint32_t)(x0 + ay1 + az1);
            i100 = (uint32_t)(x1 + ay0 + az0);
            i101 = (uint32_t)(x1 + ay0 + az1);
            i110 = (uint32_t)(x1 + ay1 + az0);
            i111 = (uint32_t)(x1 + ay1 + az1);
        } else {
            uint32_t hx0 = (uint32_t)x0,               hx1 = (uint32_t)x1;
            uint32_t hy0 = (uint32_t)y0 * 2654435761u, hy1 = (uint32_t)y1 * 2654435761u;
            uint32_t hz0 = (uint32_t)z0 * 805459861u,  hz1 = (uint32_t)z1 * 805459861u;
            i000 = (hx0 ^ hy0 ^ hz0) & HASH_MASK;
            i001 = (hx0 ^ hy0 ^ hz1) & HASH_MASK;
            i010 = (hx0 ^ hy1 ^ hz0) & HASH_MASK;
            i011 = (hx0 ^ hy1 ^ hz1) & HASH_MASK;
            i100 = (hx1 ^ hy0 ^ hz0) & HASH_MASK;
            i101 = (hx1 ^ hy0 ^ hz1) & HASH_MASK;
            i110 = (hx1 ^ hy1 ^ hz0) & HASH_MASK;
            i111 = (hx1 ^ hy1 ^ hz1) & HASH_MASK;
        }

        const float2* tb = (const float2*)tables + (size_t)l * HASH_SIZE;
        float2 t000 = __ldg(tb + i000);
        float2 t001 = __ldg(tb + i001);
        float2 t010 = __ldg(tb + i010);
        float2 t011 = __ldg(tb + i011);
        float2 t100 = __ldg(tb + i100);
        float2 t101 = __ldg(tb + i101);
        float2 t110 = __ldg(tb + i110);
        float2 t111 = __ldg(tb + i111);

        float ux = 1.0f - wx, uy = 1.0f - wy, uz = 1.0f - wz;
        float w000 = ux*uy*uz, w001 = ux*uy*wz, w010 = ux*wy*uz, w011 = ux*wy*wz;
        float w100 = wx*uy*uz, w101 = wx*uy*wz, w110 = wx*wy*uz, w111 = wx*wy*wz;

        float f0 = w000*t000.x + w001*t001.x + w010*t010.x + w011*t011.x
                 + w100*t100.x + w101*t101.x + w110*t110.x + w111*t111.x;
        float f1 = w000*t000.y + w001*t001.y + w010*t010.y + w011*t011.y
                 + w100*t100.y + w101*t101.y + w110*t110.y + w111*t111.y;

        myrow[39 + 2*l]     = tf32_of(f0);
        myrow[39 + 2*l + 1] = tf32_of(f1);
    }
    __syncwarp();

    // ---- layer0 GEMM: [32,72] x [72,64] ----
    float acc0[2][8][4];
#pragma unroll
    for (int m = 0; m < 2; m++)
#pragma unroll
        for (int nn = 0; nn < 8; nn++)
#pragma unroll
            for (int i = 0; i < 4; i++) acc0[m][nn][i] = 0.0f;

#pragma unroll 1
    for (int k = 0; k < 9; k++) {
        uint32_t bb[8][2];
#pragma unroll
        for (int nn = 0; nn < 8; nn++) {
            bb[nn][0] = sW0[(8*k + qc)*72     + 8*nn + qg];
            bb[nn][1] = sW0[(8*k + qc + 4)*72 + 8*nn + qg];
        }
#pragma unroll
        for (int m = 0; m < 2; m++) {
            const uint32_t* ar = sXw + (16*m + qg) * SX_STRIDE + 8*k;
            uint32_t a0 = ar[qc];
            uint32_t a1 = ar[8*SX_STRIDE + qc];
            uint32_t a2 = ar[qc + 4];
            uint32_t a3 = ar[8*SX_STRIDE + qc + 4];
#pragma unroll
            for (int nn = 0; nn < 8; nn++)
                mma_tf32(acc0[m][nn], a0, a1, a2, a3, bb[nn][0], bb[nn][1]);
        }
    }
    __syncwarp();

    // ---- layer1: activate per k-chunk, restage, GEMM [32,64] x [64,64] ----
    float acc1[2][8][4];
#pragma unroll
    for (int m = 0; m < 2; m++)
#pragma unroll
        for (int nn = 0; nn < 8; nn++)
#pragma unroll
            for (int i = 0; i < 4; i++) acc1[m][nn][i] = 0.0f;

#pragma unroll 1
    for (int kk = 0; kk < 8; kk++) {
        // activate acc0[.][kk] and write as A k-tile (cols 0..7 of stage)
#pragma unroll
        for (int m = 0; m < 2; m++) {
            int r0 = 16*m + qg;
            int c0 = 2*qc;
            int gc = 8*kk + c0;
            sXw[r0*SX_STRIDE + c0]         = tf32_of(sp100(acc0[m][kk][0] + sb0f[gc]));
            sXw[r0*SX_STRIDE + c0 + 1]     = tf32_of(sp100(acc0[m][kk][1] + sb0f[gc+1]));
            sXw[(r0+8)*SX_STRIDE + c0]     = tf32_of(sp100(acc0[m][kk][2] + sb0f[gc]));
            sXw[(r0+8)*SX_STRIDE + c0 + 1] = tf32_of(sp100(acc0[m][kk][3] + sb0f[gc+1]));
        }
        __syncwarp();

        uint32_t bb[8][2];
#pragma unroll
        for (int nn = 0; nn < 8; nn++) {
            bb[nn][0] = sW1[(8*kk + qc)*72     + 8*nn + qg];
            bb[nn][1] = sW1[(8*kk + qc + 4)*72 + 8*nn + qg];
        }
#pragma unroll
        for (int m = 0; m < 2; m++) {
            const uint32_t* ar = sXw + (16*m + qg) * SX_STRIDE;
            uint32_t a0 = ar[qc];
            uint32_t a1 = ar[8*SX_STRIDE + qc];
            uint32_t a2 = ar[qc + 4];
            uint32_t a3 = ar[8*SX_STRIDE + qc + 4];
#pragma unroll
            for (int nn = 0; nn < 8; nn++)
                mma_tf32(acc1[m][nn], a0, a1, a2, a3, bb[nn][0], bb[nn][1]);
        }
        __syncwarp();
    }

    // ---- layer2: activate per k-chunk, restage, GEMM [32,64] x [64,24] ----
    float acc2[2][3][4];
#pragma unroll
    for (int m = 0; m < 2; m++)
#pragma unroll
        for (int nn = 0; nn < 3; nn++)
#pragma unroll
            for (int i = 0; i < 4; i++) acc2[m][nn][i] = 0.0f;

#pragma unroll 1
    for (int kk = 0; kk < 8; kk++) {
#pragma unroll
        for (int m = 0; m < 2; m++) {
            int r0 = 16*m + qg;
            int c0 = 2*qc;
            int gc = 8*kk + c0;
            sXw[r0*SX_STRIDE + c0]         = tf32_of(sp100(acc1[m][kk][0] + sb1f[gc]));
            sXw[r0*SX_STRIDE + c0 + 1]     = tf32_of(sp100(acc1[m][kk][1] + sb1f[gc+1]));
            sXw[(r0+8)*SX_STRIDE + c0]     = tf32_of(sp100(acc1[m][kk][2] + sb1f[gc]));
            sXw[(r0+8)*SX_STRIDE + c0 + 1] = tf32_of(sp100(acc1[m][kk][3] + sb1f[gc+1]));
        }
        __syncwarp();

        uint32_t bb[3][2];
#pragma unroll
        for (int nn = 0; nn < 3; nn++) {
            bb[nn][0] = sW2[(8*kk + qc)*40     + 8*nn + qg];
            bb[nn][1] = sW2[(8*kk + qc + 4)*40 + 8*nn + qg];
        }
#pragma unroll
        for (int m = 0; m < 2; m++) {
            const uint32_t* ar = sXw + (16*m + qg) * SX_STRIDE;
            uint32_t a0 = ar[qc];
            uint32_t a1 = ar[8*SX_STRIDE + qc];
            uint32_t a2 = ar[qc + 4];
            uint32_t a3 = ar[8*SX_STRIDE + qc + 4];
#pragma unroll
            for (int nn = 0; nn < 3; nn++)
                mma_tf32(acc2[m][nn], a0, a1, a2, a3, bb[nn][0], bb[nn][1]);
        }
        __syncwarp();
    }

    // ---- epilogue: add b2, stage, coalesced scattered row writes ----
#pragma unroll
    for (int m = 0; m < 2; m++) {
#pragma unroll
        for (int nn = 0; nn < 3; nn++) {
            int r0 = 16*m + qg;
            int c0 = 8*nn + 2*qc;
#pragma unroll
            for (int i = 0; i < 4; i++) {
                int rr = r0 + ((i >= 2) ? 8 : 0);
                int cc = c0 + (i & 1);
                if (cc < 17)
                    sXw[rr*SX_STRIDE + cc] = __float_as_uint(acc2[m][nn][i] + sb2f[cc]);
            }
        }
    }
    __syncwarp();

    if (lane < 17) {
#pragma unroll 1
        for (int r = 0; r < 32; r++) {
            int gr = warpbase + r;
            if (gr < npts) {
                int rowIdx = g_perm[gr];
                out[(size_t)rowIdx*17 + lane] = __uint_as_float(sXw[r*SX_STRIDE + lane]);
            }
        }
    }
}

extern "C" void kernel_launch(void* const* d_in, const int* in_sizes, int n_in,
                              void* d_out, int out_size)
{
    const float* x  = (const float*)d_in[0];
    const float* tb = (const float*)d_in[1];
    const float* W0 = (const float*)d_in[2];
    const float* b0 = (const float*)d_in[3];
    const float* W1 = (const float*)d_in[4];
    const float* b1 = (const float*)d_in[5];
    const float* W2 = (const float*)d_in[6];
    const float* b2 = (const float*)d_in[7];
    float* out = (float*)d_out;

    int npts = in_sizes[0] / 3;

    LParams lp;
    double scale = exp2(log2(2048.0 / 16.0) / 15.0);
    for (int l = 0; l < 16; l++) {
        int R = (int)ceil(16.0 * pow(scale, (double)l));
        lp.R[l]     = R;
        lp.rm1[l]   = (float)(R - 1);
        lp.dense[l] = ((long long)R * R * R <= (long long)HASH_SIZE) ? 1 : 0;
    }

    // sort pipeline
    k_zero<<<(NBINS + 255)/256, 256>>>();
    k_hist<<<(npts + 255)/256, 256>>>(x, npts);
    k_scan1<<<NBINS/1024, 1024>>>();
    k_scan2<<<1, 256>>>();
    k_scan3<<<NBINS/1024, 1024>>>();
    k_scatter<<<(npts + 255)/256, 256>>>(npts);

    size_t smem = (size_t)(SW0_N + SW1_N + SW2_N + SX_N) * 4 + (64 + 64 + 24) * 4;
    cudaFuncSetAttribute(nerf_fused, cudaFuncAttributeMaxDynamicSharedMemorySize, (int)smem);

    int blocks = (npts + NT - 1) / NT;
    nerf_fused<<<blocks, NT, smem>>>(x, tb, W0, b0, W1, b1, W2, b2, out, npts, lp);
}

// round 8
// speedup vs baseline: 1.1093x; 1.1093x over previous
#include <cuda_runtime.h>
#include <math.h>
#include <stdint.h>

#define HASH_SIZE  (1u << 19)
#define HASH_MASK  (HASH_SIZE - 1u)
#define NT 128
#define NBINS (1 << 18)     // 64^3 Morton bins
#define MAXPTS (1 << 20)
#define CSTRIDE 68          // per-column/row float stride (quarters at 0,16,36,52)

typedef unsigned long long ull;

struct LParams {
    float rm1[16];
    int   R[16];
    int   dense[16];
};

// ---- static scratch (no allocations allowed) ----
__device__ int g_bins[NBINS];
__device__ int g_cnt[NBINS];
__device__ int g_binStart[NBINS];
__device__ int g_partials[256];
__device__ int g_keys[MAXPTS];
__device__ int g_perm[MAXPTS];

__device__ __forceinline__ void fma2(ull &acc, ull a, ull b) {
    asm("fma.rn.f32x2 %0, %1, %2, %0;" : "+l"(acc) : "l"(a), "l"(b));
}
__device__ __forceinline__ ull pack2(float x, float y) {
    ull r; asm("mov.b64 %0, {%1, %2};" : "=l"(r) : "f"(x), "f"(y)); return r;
}
__device__ __forceinline__ float2 unpack2(ull v) {
    float2 r; asm("mov.b64 {%0, %1}, %2;" : "=f"(r.x), "=f"(r.y) : "l"(v)); return r;
}

// fast softplus100: MUFU-based. Exact in linear region (z>20); abs err ~1e-8 otherwise.
__device__ __forceinline__ float sp100(float v) {
    float z = v * 100.0f;
    float s = 0.01f * __logf(1.0f + __expf(z));
    return (z > 20.0f) ? v : s;
}

// ---------------- sort pipeline ----------------
__device__ __forceinline__ uint32_t part3(uint32_t x) {
    x &= 0x3Fu;
    x = (x | (x << 16)) & 0x030000FFu;
    x = (x | (x << 8))  & 0x0300F00Fu;
    x = (x | (x << 4))  & 0x030C30C3u;
    x = (x | (x << 2))  & 0x09249249u;
    return x;
}
__global__ void k_zero() {
    int i = blockIdx.x * blockDim.x + threadIdx.x;
    if (i < NBINS) { g_bins[i] = 0; g_cnt[i] = 0; }
}
__global__ void k_hist(const float* __restrict__ x, int npts) {
    int i = blockIdx.x * blockDim.x + threadIdx.x;
    if (i >= npts) return;
    float px = x[3*i], py = x[3*i+1], pz = x[3*i+2];
    int kx = min(max((int)(px * 64.0f), 0), 63);
    int ky = min(max((int)(py * 64.0f), 0), 63);
    int kz = min(max((int)(pz * 64.0f), 0), 63);
    uint32_t key = part3(kx) | (part3(ky) << 1) | (part3(kz) << 2);
    g_keys[i] = (int)key;
    atomicAdd(&g_bins[key], 1);
}
__global__ void k_scan1() {
    __shared__ int s[1024];
    int t = threadIdx.x;
    int g = blockIdx.x * 1024 + t;
    int v = g_bins[g];
    s[t] = v; __syncthreads();
#pragma unroll
    for (int d = 1; d < 1024; d <<= 1) {
        int add = (t >= d) ? s[t-d] : 0;
        __syncthreads();
        s[t] += add;
        __syncthreads();
    }
    g_binStart[g] = s[t] - v;
    if (t == 1023) g_partials[blockIdx.x] = s[t];
}
__global__ void k_scan2() {
    __shared__ int s[256];
    int t = threadIdx.x;
    int v = g_partials[t];
    s[t] = v; __syncthreads();
#pragma unroll
    for (int d = 1; d < 256; d <<= 1) {
        int add = (t >= d) ? s[t-d] : 0;
        __syncthreads();
        s[t] += add;
        __syncthreads();
    }
    g_partials[t] = s[t] - v;
}
__global__ void k_scan3() {
    int g = blockIdx.x * 1024 + threadIdx.x;
    g_binStart[g] += g_partials[blockIdx.x];
}
__global__ void k_scatter(int npts) {
    int i = blockIdx.x * blockDim.x + threadIdx.x;
    if (i >= npts) return;
    int k = g_keys[i];
    int pos = g_binStart[k] + atomicAdd(&g_cnt[k], 1);
    g_perm[pos] = i;
}

// ---------------- fused main kernel (4-lane quarter split) ----------------
// acc[k] holds this lane's 16 hidden units for point (lane ^ k) of its lane-quad.
__device__ __forceinline__ void addin4(ull a0[8], ull a1[8], ull a2[8], ull a3[8],
                                       float v0, float v1, float v2, float v3,
                                       const float* col16) {
    const ulonglong2* c = (const ulonglong2*)col16;   // 4 x 16B = 16 floats
    ull p0 = pack2(v0, v0);
    ull p1 = pack2(v1, v1);
    ull p2 = pack2(v2, v2);
    ull p3 = pack2(v3, v3);
#pragma unroll
    for (int t = 0; t < 4; t++) {
        ulonglong2 w = c[t];
        fma2(a0[2*t+0], p0, w.x); fma2(a0[2*t+1], p0, w.y);
        fma2(a1[2*t+0], p1, w.x); fma2(a1[2*t+1], p1, w.y);
        fma2(a2[2*t+0], p2, w.x); fma2(a2[2*t+1], p2, w.y);
        fma2(a3[2*t+0], p3, w.x); fma2(a3[2*t+1], p3, w.y);
    }
}

#define ADDIN4(v, colp)                                          \
    do {                                                         \
        float _v  = (v);                                         \
        float _v1 = __shfl_xor_sync(0xffffffffu, _v, 1);         \
        float _v2 = __shfl_xor_sync(0xffffffffu, _v, 2);         \
        float _v3 = __shfl_xor_sync(0xffffffffu, _v, 3);         \
        addin4(acc[0], acc[1], acc[2], acc[3], _v, _v1, _v2, _v3, (colp)); \
    } while (0)

__global__ void __launch_bounds__(NT, 4) nerf_fused(
    const float* __restrict__ xin,
    const float* __restrict__ tables,
    const float* __restrict__ W0, const float* __restrict__ b0,
    const float* __restrict__ W1, const float* __restrict__ b1,
    const float* __restrict__ W2, const float* __restrict__ b2,
    float* __restrict__ out, int npts, LParams lp)
{
    __shared__ __align__(16) float sW0T[71*CSTRIDE];  // col i: quarter q at i*68+qoff(q); reused as out stage
    __shared__ __align__(16) float sW1p[64*CSTRIDE];  // row r: same quarter layout
    __shared__ __align__(16) float sW2T[64*20];       // sW2T[j*20+o] = W2[o][j]
    __shared__ float sb0[64];
    __shared__ float sb1[64];
    __shared__ float sb2p[20];
    __shared__ int   sRow[NT];

    const int tid = threadIdx.x;
    for (int k = tid; k < 71*64; k += NT) {
        int i = k >> 6, j = k & 63;
        int q = j >> 4;
        int jo = q*16 + (q>>1)*4 + (j & 15);          // 0,16,36,52 quarter bases
        sW0T[i*CSTRIDE + jo] = W0[j*71 + i];
    }
    for (int k = tid; k < 64*64; k += NT) {
        int r = k >> 6, j = k & 63;
        int q = j >> 4;
        int jo = q*16 + (q>>1)*4 + (j & 15);
        sW1p[r*CSTRIDE + jo] = W1[k];
    }
    for (int k = tid; k < 64*20; k += NT) {
        int j = k / 20, o = k % 20;
        sW2T[k] = (o < 17) ? W2[o*64 + j] : 0.0f;
    }
    if (tid < 64) { sb0[tid] = b0[tid]; sb1[tid] = b1[tid]; }
    if (tid < 20) sb2p[tid] = (tid < 17) ? b2[tid] : 0.0f;
    __syncthreads();

    const int gid = blockIdx.x * NT + tid;
    const bool valid = (gid < npts);
    const int n = valid ? g_perm[gid] : g_perm[0];
    const int quart = tid & 3;
    const int qoff = quart*16 + (quart>>1)*4;
    const float* colQ = sW0T + qoff;

    const float px = xin[n*3+0], py = xin[n*3+1], pz = xin[n*3+2];

    ull acc[4][8];
#pragma unroll
    for (int t = 0; t < 8; t++) {
        ull bv = pack2(sb0[quart*16 + 2*t], sb0[quart*16 + 2*t + 1]);
        acc[0][t] = bv; acc[1][t] = bv; acc[2][t] = bv; acc[3][t] = bv;
    }

    // inputs 0..2
    ADDIN4(px, colQ + 0*CSTRIDE);
    ADDIN4(py, colQ + 1*CSTRIDE);
    ADDIN4(pz, colQ + 2*CSTRIDE);

    // inputs 3..38: positional embedding (fast MUFU trig)
#pragma unroll 1
    for (int m = 0; m < 6; m++) {
        float f = (float)(1 << m);
        float ax = px * f, ay = py * f, az = pz * f;
        float sx = __sinf(ax), cx = __cosf(ax);
        float sy = __sinf(ay), cy = __cosf(ay);
        float sz = __sinf(az), cz = __cosf(az);
        const float* base = colQ + (3 + 6*m) * CSTRIDE;
        ADDIN4(sx, base + 0*CSTRIDE);
        ADDIN4(sy, base + 1*CSTRIDE);
        ADDIN4(sz, base + 2*CSTRIDE);
        ADDIN4(cx, base + 3*CSTRIDE);
        ADDIN4(cy, base + 4*CSTRIDE);
        ADDIN4(cz, base + 5*CSTRIDE);
    }

    // inputs 39..70: hash-grid features
#pragma unroll 1
    for (int l = 0; l < 16; l++) {
        const float rm1 = lp.rm1[l];
        const int   R   = lp.R[l];
        float fx = px * rm1, fy = py * rm1, fz = pz * rm1;
        float p0x = floorf(fx), p0y = floorf(fy), p0z = floorf(fz);
        float wx = fx - p0x, wy = fy - p0y, wz = fz - p0z;
        int ix = (int)p0x, iy = (int)p0y, iz = (int)p0z;
        int x0 = max(min(ix,     R-1), 0), x1 = max(min(ix + 1, R-1), 0);
        int y0 = max(min(iy,     R-1), 0), y1 = max(min(iy + 1, R-1), 0);
        int z0 = max(min(iz,     R-1), 0), z1 = max(min(iz + 1, R-1), 0);

        uint32_t i000, i001, i010, i011, i100, i101, i110, i111;
        if (lp.dense[l]) {
            int R2 = R * R;
            int az0 = z0 * R2, az1 = z1 * R2;
            int ay0 = y0 * R,  ay1 = y1 * R;
            i000 = (uint32_t)(x0 + ay0 + az0);
            i001 = (uint32_t)(x0 + ay0 + az1);
            i010 = (uint32_t)(x0 + ay1 + az0);
            i011 = (uint32_t)(x0 + ay1 + az1);
            i100 = (uint32_t)(x1 + ay0 + az0);
            i101 = (uint32_t)(x1 + ay0 + az1);
            i110 = (uint32_t)(x1 + ay1 + az0);
            i111 = (uint32_t)(x1 + ay1 + az1);
        } else {
            uint32_t hx0 = (uint32_t)x0,               hx1 = (uint32_t)x1;
            uint32_t hy0 = (uint32_t)y0 * 2654435761u, hy1 = (uint32_t)y1 * 2654435761u;
            uint32_t hz0 = (uint32_t)z0 * 805459861u,  hz1 = (uint32_t)z1 * 805459861u;
            i000 = (hx0 ^ hy0 ^ hz0) & HASH_MASK;
            i001 = (hx0 ^ hy0 ^ hz1) & HASH_MASK;
            i010 = (hx0 ^ hy1 ^ hz0) & HASH_MASK;
            i011 = (hx0 ^ hy1 ^ hz1) & HASH_MASK;
            i100 = (hx1 ^ hy0 ^ hz0) & HASH_MASK;
            i101 = (hx1 ^ hy0 ^ hz1) & HASH_MASK;
            i110 = (hx1 ^ hy1 ^ hz0) & HASH_MASK;
            i111 = (hx1 ^ hy1 ^ hz1) & HASH_MASK;
        }

        const float2* tb = (const float2*)tables + (size_t)l * HASH_SIZE;
        float2 t000 = __ldg(tb + i000);
        float2 t001 = __ldg(tb + i001);
        float2 t010 = __ldg(tb + i010);
        float2 t011 = __ldg(tb + i011);
        float2 t100 = __ldg(tb + i100);
        float2 t101 = __ldg(tb + i101);
        float2 t110 = __ldg(tb + i110);
        float2 t111 = __ldg(tb + i111);

        float ux = 1.0f - wx, uy = 1.0f - wy, uz = 1.0f - wz;
        float w000 = ux*uy*uz, w001 = ux*uy*wz, w010 = ux*wy*uz, w011 = ux*wy*wz;
        float w100 = wx*uy*uz, w101 = wx*uy*wz, w110 = wx*wy*uz, w111 = wx*wy*wz;

        float f0 = w000*t000.x + w001*t001.x + w010*t010.x + w011*t011.x
                 + w100*t100.x + w101*t101.x + w110*t110.x + w111*t111.x;
        float f1 = w000*t000.y + w001*t001.y + w010*t010.y + w011*t011.y
                 + w100*t100.y + w101*t101.y + w110*t110.y + w111*t111.y;

        const float* colp = colQ + (39 + 2*l) * CSTRIDE;
        ADDIN4(f0, colp);
        ADDIN4(f1, colp + CSTRIDE);
    }

    // activation
#pragma unroll
    for (int k = 0; k < 4; k++)
#pragma unroll
        for (int t = 0; t < 8; t++) {
            float2 a = unpack2(acc[k][t]);
            acc[k][t] = pack2(sp100(a.x), sp100(a.y));
        }

    // layers 1+2 fused
    ull o17[9];
#pragma unroll
    for (int t = 0; t < 9; t++) o17[t] = pack2(sb2p[2*t], sb2p[2*t+1]);

#pragma unroll 2
    for (int r = 0; r < 64; r++) {
        const ulonglong2* wr = (const ulonglong2*)(sW1p + r*CSTRIDE + qoff);
        ull s0 = 0, s1 = 0, s2 = 0, s3 = 0;
#pragma unroll
        for (int t = 0; t < 4; t++) {
            ulonglong2 w = wr[t];
            fma2(s0, w.x, acc[0][2*t+0]); fma2(s0, w.y, acc[0][2*t+1]);
            fma2(s1, w.x, acc[1][2*t+0]); fma2(s1, w.y, acc[1][2*t+1]);
            fma2(s2, w.x, acc[2][2*t+0]); fma2(s2, w.y, acc[2][2*t+1]);
            fma2(s3, w.x, acc[3][2*t+0]); fma2(s3, w.y, acc[3][2*t+1]);
        }
        float2 f0v = unpack2(s0), f1v = unpack2(s1), f2v = unpack2(s2), f3v = unpack2(s3);
        float t0 = f0v.x + f0v.y;       // partial for point lane^0 (own quarter)
        float t1 = f1v.x + f1v.y;       // point lane^1
        float t2 = f2v.x + f2v.y;       // point lane^2
        float t3 = f3v.x + f3v.y;       // point lane^3
        float a0 = t0 + __shfl_xor_sync(0xffffffffu, t1, 1);  // point 'lane' over quarts {q,q^1}
        float a2 = t2 + __shfl_xor_sync(0xffffffffu, t3, 1);  // point 'lane^2' over quarts {q,q^1}
        float h  = a0 + __shfl_xor_sync(0xffffffffu, a2, 2) + sb1[r];
        float v = sp100(h);
        ull vv = pack2(v, v);
        const ulonglong2* w2q = (const ulonglong2*)(sW2T + r*20);
#pragma unroll
        for (int q = 0; q < 4; q++) {
            ulonglong2 w = w2q[q];
            fma2(o17[2*q+0], vv, w.x);
            fma2(o17[2*q+1], vv, w.y);
        }
        fma2(o17[8], vv, *(const ull*)(sW2T + r*20 + 16));
    }

    // ---- stage outputs to smem (reuse sW0T), then warp-cooperative scattered row writes ----
    __syncthreads();                   // everyone done reading sW0T
    float* stage = sW0T;               // 128*17 = 2176 floats < 71*68
    sRow[tid] = valid ? n : -1;
#pragma unroll
    for (int t = 0; t < 8; t++) {
        float2 v = unpack2(o17[t]);
        stage[tid*17 + 2*t + 0] = v.x;
        stage[tid*17 + 2*t + 1] = v.y;
    }
    stage[tid*17 + 16] = unpack2(o17[8]).x;
    __syncthreads();

    const int wid = tid >> 5, lane = tid & 31;
    if (lane < 17) {
#pragma unroll 1
        for (int r = wid*32; r < wid*32 + 32; r++) {
            int rowIdx = sRow[r];
            if (rowIdx >= 0) out[(size_t)rowIdx*17 + lane] = stage[r*17 + lane];
        }
    }
}

extern "C" void kernel_launch(void* const* d_in, const int* in_sizes, int n_in,
                              void* d_out, int out_size)
{
    const float* x  = (const float*)d_in[0];
    const float* tb = (const float*)d_in[1];
    const float* W0 = (const float*)d_in[2];
    const float* b0 = (const float*)d_in[3];
    const float* W1 = (const float*)d_in[4];
    const float* b1 = (const float*)d_in[5];
    const float* W2 = (const float*)d_in[6];
    const float* b2 = (const float*)d_in[7];
    float* out = (float*)d_out;

    int npts = in_sizes[0] / 3;

    LParams lp;
    double scale = exp2(log2(2048.0 / 16.0) / 15.0);
    for (int l = 0; l < 16; l++) {
        int R = (int)ceil(16.0 * pow(scale, (double)l));
        lp.R[l]     = R;
        lp.rm1[l]   = (float)(R - 1);
        lp.dense[l] = ((long long)R * R * R <= (long long)HASH_SIZE) ? 1 : 0;
    }

    // ---- sort pipeline ----
    k_zero<<<(NBINS + 255)/256, 256>>>();
    k_hist<<<(npts + 255)/256, 256>>>(x, npts);
    k_scan1<<<NBINS/1024, 1024>>>();
    k_scan2<<<1, 256>>>();
    k_scan3<<<NBINS/1024, 1024>>>();
    k_scatter<<<(npts + 255)/256, 256>>>(npts);

    // ---- fused main ----
    int blocks = (npts + NT - 1) / NT;
    nerf_fused<<<blocks, NT>>>(x, tb, W0, b0, W1, b1, W2, b2, out, npts, lp);
}

// round 9
// speedup vs baseline: 1.7344x; 1.5635x over previous
#include <cuda_runtime.h>
#include <math.h>
#include <stdint.h>

#define HASH_SIZE  (1u << 19)
#define HASH_MASK  (HASH_SIZE - 1u)
#define NT 128
#define NBINS (1 << 18)     // 64^3 Morton bins
#define MAXPTS (1 << 20)

typedef unsigned long long ull;

struct LParams {
    float rm1[16];
    int   R[16];
    int   dense[16];
};

// ---- static scratch (no allocations allowed) ----
__device__ int g_bins[NBINS];
__device__ int g_cnt[NBINS];
__device__ int g_binStart[NBINS];
__device__ int g_partials[256];
__device__ int g_keys[MAXPTS];
__device__ int g_perm[MAXPTS];

__device__ __forceinline__ void fma2(ull &acc, ull a, ull b) {
    asm("fma.rn.f32x2 %0, %1, %2, %0;" : "+l"(acc) : "l"(a), "l"(b));
}
__device__ __forceinline__ ull pack2(float x, float y) {
    ull r; asm("mov.b64 %0, {%1, %2};" : "=l"(r) : "f"(x), "f"(y)); return r;
}
__device__ __forceinline__ float2 unpack2(ull v) {
    float2 r; asm("mov.b64 {%0, %1}, %2;" : "=f"(r.x), "=f"(r.y) : "l"(v)); return r;
}

// fast softplus100: MUFU-based. Exact in linear region (z>20); abs err ~1e-8 otherwise.
__device__ __forceinline__ float sp100(float v) {
    float z = v * 100.0f;
    float s = 0.01f * __logf(1.0f + __expf(z));
    return (z > 20.0f) ? v : s;
}

// ---------------- sort pipeline ----------------
__device__ __forceinline__ uint32_t part3(uint32_t x) {
    x &= 0x3Fu;
    x = (x | (x << 16)) & 0x030000FFu;
    x = (x | (x << 8))  & 0x0300F00Fu;
    x = (x | (x << 4))  & 0x030C30C3u;
    x = (x | (x << 2))  & 0x09249249u;
    return x;
}
__global__ void k_zero() {
    int i = blockIdx.x * blockDim.x + threadIdx.x;
    if (i < NBINS) { g_bins[i] = 0; g_cnt[i] = 0; }
}
__global__ void k_hist(const float* __restrict__ x, int npts) {
    int i = blockIdx.x * blockDim.x + threadIdx.x;
    if (i >= npts) return;
    float px = x[3*i], py = x[3*i+1], pz = x[3*i+2];
    int kx = min(max((int)(px * 64.0f), 0), 63);
    int ky = min(max((int)(py * 64.0f), 0), 63);
    int kz = min(max((int)(pz * 64.0f), 0), 63);
    uint32_t key = part3(kx) | (part3(ky) << 1) | (part3(kz) << 2);
    g_keys[i] = (int)key;
    atomicAdd(&g_bins[key], 1);
}
__global__ void k_scan1() {            // 256 blocks x 1024: per-block exclusive scan
    __shared__ int s[1024];
    int t = threadIdx.x;
    int g = blockIdx.x * 1024 + t;
    int v = g_bins[g];
    s[t] = v; __syncthreads();
#pragma unroll
    for (int d = 1; d < 1024; d <<= 1) {
        int add = (t >= d) ? s[t-d] : 0;
        __syncthreads();
        s[t] += add;
        __syncthreads();
    }
    g_binStart[g] = s[t] - v;
    if (t == 1023) g_partials[blockIdx.x] = s[t];
}
__global__ void k_scan2() {            // 1 block x 256: exclusive scan of block totals
    __shared__ int s[256];
    int t = threadIdx.x;
    int v = g_partials[t];
    s[t] = v; __syncthreads();
#pragma unroll
    for (int d = 1; d < 256; d <<= 1) {
        int add = (t >= d) ? s[t-d] : 0;
        __syncthreads();
        s[t] += add;
        __syncthreads();
    }
    g_partials[t] = s[t] - v;
}
// scan3 folded in: global bin start = binStart[k] + partials[k>>10]
__global__ void k_scatter(int npts) {
    int i = blockIdx.x * blockDim.x + threadIdx.x;
    if (i >= npts) return;
    int k = g_keys[i];
    int pos = g_binStart[k] + g_partials[k >> 10] + atomicAdd(&g_cnt[k], 1);
    g_perm[pos] = i;
}

// ---------------- fused main kernel ----------------
__device__ __forceinline__ void addin2(ull accS[16], ull accO[16],
                                       float vS, float vO, const float* col32) {
    const ulonglong2* c = (const ulonglong2*)col32;
    ull a = pack2(vS, vS);
    ull b = pack2(vO, vO);
#pragma unroll
    for (int q = 0; q < 8; q++) {
        ulonglong2 w = c[q];
        fma2(accS[2*q+0], a, w.x);
        fma2(accS[2*q+1], a, w.y);
        fma2(accO[2*q+0], b, w.x);
        fma2(accO[2*q+1], b, w.y);
    }
}

__global__ void __launch_bounds__(NT, 4) nerf_fused(
    const float* __restrict__ xin,
    const float* __restrict__ tables,
    const float* __restrict__ W0, const float* __restrict__ b0,
    const float* __restrict__ W1, const float* __restrict__ b1,
    const float* __restrict__ W2, const float* __restrict__ b2,
    float* __restrict__ out, int npts, LParams lp)
{
    __shared__ __align__(16) float sW0T[71*72];   // col i: even half at +0, odd at +36; reused as out stage
    __shared__ __align__(16) float sW1p[64*72];
    __shared__ __align__(16) float sW2T[64*20];
    __shared__ float sb0[64];
    __shared__ float sb1[64];
    __shared__ float sb2p[20];
    __shared__ int   sRow[NT];

    const int tid = threadIdx.x;
    for (int k = tid; k < 71*64; k += NT) {
        int i = k >> 6, j = k & 63;
        int jo = (j < 32) ? j : (j + 4);           // odd half at +36
        sW0T[i*72 + jo] = W0[j*71 + i];
    }
    for (int k = tid; k < 64*64; k += NT) {
        int r = k >> 6, j = k & 63;
        int jo = (j < 32) ? j : (j + 4);
        sW1p[r*72 + jo] = W1[k];
    }
    for (int k = tid; k < 64*20; k += NT) {
        int j = k / 20, o = k % 20;
        sW2T[k] = (o < 17) ? W2[o*64 + j] : 0.0f;
    }
    if (tid < 64) { sb0[tid] = b0[tid]; sb1[tid] = b1[tid]; }
    if (tid < 20) sb2p[tid] = (tid < 17) ? b2[tid] : 0.0f;
    __syncthreads();

    const int gid = blockIdx.x * NT + tid;
    const bool valid = (gid < npts);
    const int n = valid ? g_perm[gid] : g_perm[0];
    const int half = tid & 1;
    const float* colHalf = sW0T + half * 36;

    const float px = xin[n*3+0], py = xin[n*3+1], pz = xin[n*3+2];

    ull accS[16], accO[16];
    const int hb = half * 32;
#pragma unroll
    for (int q = 0; q < 16; q++) {
        ull bv = pack2(sb0[hb + 2*q], sb0[hb + 2*q + 1]);
        accS[q] = bv;
        accO[q] = bv;
    }

    // inputs 0..2
    {
        float vO;
        vO = __shfl_xor_sync(0xffffffffu, px, 1); addin2(accS, accO, px, vO, colHalf + 0*72);
        vO = __shfl_xor_sync(0xffffffffu, py, 1); addin2(accS, accO, py, vO, colHalf + 1*72);
        vO = __shfl_xor_sync(0xffffffffu, pz, 1); addin2(accS, accO, pz, vO, colHalf + 2*72);
    }

    // inputs 3..38: positional embedding (fast MUFU trig; angle <= 32 rad)
#pragma unroll 1
    for (int m = 0; m < 6; m++) {
        float f = (float)(1 << m);
        float ax = px * f, ay = py * f, az = pz * f;
        float sx = __sinf(ax), cx = __cosf(ax);
        float sy = __sinf(ay), cy = __cosf(ay);
        float sz = __sinf(az), cz = __cosf(az);
        const float* base = colHalf + (3 + 6*m) * 72;
        float vO;
        vO = __shfl_xor_sync(0xffffffffu, sx, 1); addin2(accS, accO, sx, vO, base + 0*72);
        vO = __shfl_xor_sync(0xffffffffu, sy, 1); addin2(accS, accO, sy, vO, base + 1*72);
        vO = __shfl_xor_sync(0xffffffffu, sz, 1); addin2(accS, accO, sz, vO, base + 2*72);
        vO = __shfl_xor_sync(0xffffffffu, cx, 1); addin2(accS, accO, cx, vO, base + 3*72);
        vO = __shfl_xor_sync(0xffffffffu, cy, 1); addin2(accS, accO, cy, vO, base + 4*72);
        vO = __shfl_xor_sync(0xffffffffu, cz, 1); addin2(accS, accO, cz, vO, base + 5*72);
    }

    // inputs 39..70: hash-grid features
#pragma unroll 1
    for (int l = 0; l < 16; l++) {
        const float rm1 = lp.rm1[l];
        const int   R   = lp.R[l];
        float fx = px * rm1, fy = py * rm1, fz = pz * rm1;
        float p0x = floorf(fx), p0y = floorf(fy), p0z = floorf(fz);
        float wx = fx - p0x, wy = fy - p0y, wz = fz - p0z;
        int ix = (int)p0x, iy = (int)p0y, iz = (int)p0z;
        int x0 = max(min(ix,     R-1), 0), x1 = max(min(ix + 1, R-1), 0);
        int y0 = max(min(iy,     R-1), 0), y1 = max(min(iy + 1, R-1), 0);
        int z0 = max(min(iz,     R-1), 0), z1 = max(min(iz + 1, R-1), 0);

        uint32_t i000, i001, i010, i011, i100, i101, i110, i111;
        if (lp.dense[l]) {
            int R2 = R * R;
            int az0 = z0 * R2, az1 = z1 * R2;
            int ay0 = y0 * R,  ay1 = y1 * R;
            i000 = (uint32_t)(x0 + ay0 + az0);
            i001 = (uint32_t)(x0 + ay0 + az1);
            i010 = (uint32_t)(x0 + ay1 + az0);
            i011 = (uint32_t)(x0 + ay1 + az1);
            i100 = (uint32_t)(x1 + ay0 + az0);
            i101 = (uint32_t)(x1 + ay0 + az1);
            i110 = (uint32_t)(x1 + ay1 + az0);
            i111 = (uint32_t)(x1 + ay1 + az1);
        } else {
            // PRIME0 == 1: h = x ^ (y*P1) ^ (z*P2). Precompute the 4 y/z combos.
            uint32_t hy0 = (uint32_t)y0 * 2654435761u, hy1 = (uint32_t)y1 * 2654435761u;
            uint32_t hz0 = (uint32_t)z0 * 805459861u,  hz1 = (uint32_t)z1 * 805459861u;
            uint32_t a00 = hy0 ^ hz0, a01 = hy0 ^ hz1;
            uint32_t a10 = hy1 ^ hz0, a11 = hy1 ^ hz1;
            uint32_t ux0 = (uint32_t)x0, ux1 = (uint32_t)x1;
            i000 = (ux0 ^ a00) & HASH_MASK;
            i001 = (ux0 ^ a01) & HASH_MASK;
            i010 = (ux0 ^ a10) & HASH_MASK;
            i011 = (ux0 ^ a11) & HASH_MASK;
            i100 = (ux1 ^ a00) & HASH_MASK;
            i101 = (ux1 ^ a01) & HASH_MASK;
            i110 = (ux1 ^ a10) & HASH_MASK;
            i111 = (ux1 ^ a11) & HASH_MASK;
        }

        const float2* tb = (const float2*)tables + (size_t)l * HASH_SIZE;
        float2 t000 = __ldg(tb + i000);
        float2 t001 = __ldg(tb + i001);
        float2 t010 = __ldg(tb + i010);
        float2 t011 = __ldg(tb + i011);
        float2 t100 = __ldg(tb + i100);
        float2 t101 = __ldg(tb + i101);
        float2 t110 = __ldg(tb + i110);
        float2 t111 = __ldg(tb + i111);

        float ux = 1.0f - wx, uy = 1.0f - wy, uz = 1.0f - wz;
        float w000 = ux*uy*uz, w001 = ux*uy*wz, w010 = ux*wy*uz, w011 = ux*wy*wz;
        float w100 = wx*uy*uz, w101 = wx*uy*wz, w110 = wx*wy*uz, w111 = wx*wy*wz;

        float f0 = w000*t000.x + w001*t001.x + w010*t010.x + w011*t011.x
                 + w100*t100.x + w101*t101.x + w110*t110.x + w111*t111.x;
        float f1 = w000*t000.y + w001*t001.y + w010*t010.y + w011*t011.y
                 + w100*t100.y + w101*t101.y + w110*t110.y + w111*t111.y;

        const float* colp = colHalf + (39 + 2*l) * 72;
        float f0O = __shfl_xor_sync(0xffffffffu, f0, 1);
        float f1O = __shfl_xor_sync(0xffffffffu, f1, 1);
        addin2(accS, accO, f0, f0O, colp);
        addin2(accS, accO, f1, f1O, colp + 72);
    }

    // activation
#pragma unroll
    for (int q = 0; q < 16; q++) {
        float2 a = unpack2(accS[q]);
        accS[q] = pack2(sp100(a.x), sp100(a.y));
        float2 b = unpack2(accO[q]);
        accO[q] = pack2(sp100(b.x), sp100(b.y));
    }

    // layers 1+2 fused
    ull o17[9];
#pragma unroll
    for (int t = 0; t < 9; t++) o17[t] = pack2(sb2p[2*t], sb2p[2*t+1]);

#pragma unroll 2
    for (int r = 0; r < 64; r++) {
        const ulonglong2* wr = (const ulonglong2*)(sW1p + r*72 + half*36);
        ull sS = 0, sO = 0;
#pragma unroll
        for (int q = 0; q < 8; q++) {
            ulonglong2 w = wr[q];
            fma2(sS, w.x, accS[2*q+0]);
            fma2(sS, w.y, accS[2*q+1]);
            fma2(sO, w.x, accO[2*q+0]);
            fma2(sO, w.y, accO[2*q+1]);
        }
        float2 fs = unpack2(sS);
        float2 fo = unpack2(sO);
        float pS = fs.x + fs.y;
        float pO = fo.x + fo.y;
        float cross = __shfl_xor_sync(0xffffffffu, pO, 1);
        float v = sp100(pS + cross + sb1[r]);
        ull vv = pack2(v, v);
        const ulonglong2* w2q = (const ulonglong2*)(sW2T + r*20);
#pragma unroll
        for (int q = 0; q < 4; q++) {
            ulonglong2 w = w2q[q];
            fma2(o17[2*q+0], vv, w.x);
            fma2(o17[2*q+1], vv, w.y);
        }
        fma2(o17[8], vv, *(const ull*)(sW2T + r*20 + 16));
    }

    // ---- stage outputs to smem (reuse sW0T), then warp-cooperative scattered row writes ----
    __syncthreads();                   // everyone done reading sW0T
    float* stage = sW0T;               // 128*17 = 2176 floats < 71*72
    sRow[tid] = valid ? n : -1;
#pragma unroll
    for (int t = 0; t < 8; t++) {
        float2 v = unpack2(o17[t]);
        stage[tid*17 + 2*t + 0] = v.x;
        stage[tid*17 + 2*t + 1] = v.y;
    }
    stage[tid*17 + 16] = unpack2(o17[8]).x;
    __syncthreads();

    const int wid = tid >> 5, lane = tid & 31;
    if (lane < 17) {
#pragma unroll 1
        for (int r = wid*32; r < wid*32 + 32; r++) {
            int rowIdx = sRow[r];
            if (rowIdx >= 0) out[(size_t)rowIdx*17 + lane] = stage[r*17 + lane];
        }
    }
}

extern "C" void kernel_launch(void* const* d_in, const int* in_sizes, int n_in,
                              void* d_out, int out_size)
{
    const float* x  = (const float*)d_in[0];
    const float* tb = (const float*)d_in[1];
    const float* W0 = (const float*)d_in[2];
    const float* b0 = (const float*)d_in[3];
    const float* W1 = (const float*)d_in[4];
    const float* b1 = (const float*)d_in[5];
    const float* W2 = (const float*)d_in[6];
    const float* b2 = (const float*)d_in[7];
    float* out = (float*)d_out;

    int npts = in_sizes[0] / 3;

    LParams lp;
    double scale = exp2(log2(2048.0 / 16.0) / 15.0);
    for (int l = 0; l < 16; l++) {
        int R = (int)ceil(16.0 * pow(scale, (double)l));
        lp.R[l]     = R;
        lp.rm1[l]   = (float)(R - 1);
        lp.dense[l] = ((long long)R * R * R <= (long long)HASH_SIZE) ? 1 : 0;
    }

    // ---- sort pipeline (5 launches; nerf_fused is launch #6 for ncu -s 5 -c 1) ----
    k_zero<<<(NBINS + 255)/256, 256>>>();
    k_hist<<<(npts + 255)/256, 256>>>(x, npts);
    k_scan1<<<NBINS/1024, 1024>>>();
    k_scan2<<<1, 256>>>();
    k_scatter<<<(npts + 255)/256, 256>>>(npts);

    // ---- fused main ----
    int blocks = (npts + NT - 1) / NT;
    nerf_fused<<<blocks, NT>>>(x, tb, W0, b0, W1, b1, W2, b2, out, npts, lp);
}